// round 9
// baseline (speedup 1.0000x reference)
#include <cuda_runtime.h>
#include <cuda_fp16.h>
#include <math.h>

// CollectNeighbourAverageAndMax: out[v] = concat(mean_k x[idx[v,k]], max_k x[idx[v,k]])
// V=100000, K=32, F=64.
//
// R6: R4 structure (best: main 33.6us) with ONE change: gathers use __ldcg
// (ld.global.cg -> cache at L2, no L1 allocation).
// Evidence: L1 busy is ~2.2 cyc per distinct 128B line regardless of LDG
// width/count (R4 vs R5), i.e. per-line allocate+fill+evict churn on a 12.8MB
// stream through 228KB L1 at ~2% hit rate. Bypassing L1 allocation should cut
// the per-line cost toward the 1.0 cyc/wf streaming rate and stop the thrash.
//  - fp16 mirror (12.8MB static): one row = 128B = one L1 line.
//  - one warp per output row; lane l owns features (2l, 2l+1) as one half2.
//  - 32x warp-wide LDG.32 gathers (one line each), batches of 8 for MLP.
//  - max in half2 (exact); sum tree-of-8 in fp16 then fp32 promote per chunk.

#define VV 100000
#define KK 32
#define FF 64
#define ROW_H2 (FF / 2)   // 32 half2 per row

__device__ __half2 g_xh[(size_t)VV * ROW_H2];   // 12.8 MB static scratch

// ---- prepass: fp32 -> fp16 conversion ------------------------------------
__global__ void convert_kernel(const float* __restrict__ x) {
    const int i = blockIdx.x * blockDim.x + threadIdx.x;  // one float4 -> two half2
    const int n4 = VV * FF / 4;
    if (i >= n4) return;
    const float4 v = reinterpret_cast<const float4*>(x)[i];
    g_xh[2 * i]     = __floats2half2_rn(v.x, v.y);
    g_xh[2 * i + 1] = __floats2half2_rn(v.z, v.w);
}

__device__ __forceinline__ __half2 u2h(unsigned u) {
    return *reinterpret_cast<__half2*>(&u);
}

// ---- main gather/reduce ---------------------------------------------------
__global__ __launch_bounds__(256, 8)
void collect_nbr_kernel(const int* __restrict__ idxs,
                        float* __restrict__ out) {
    const int row  = (blockIdx.x * blockDim.x + threadIdx.x) >> 5;
    const int lane = threadIdx.x & 31;
    if (row >= VV) return;

    // Each lane holds one neighbor index (coalesced 128B load).
    const int my_idx = __ldg(idxs + (size_t)row * KK + lane);

    float2  sum = make_float2(0.f, 0.f);
    __half2 mx  = u2h(0xFBFFFBFFu);    // half2(-65504, -65504)

    const unsigned* __restrict__ xb =
        reinterpret_cast<const unsigned*>(g_xh) + lane;  // lane's slot in any row

    #pragma unroll
    for (int c = 0; c < KK / 8; c++) {
        // Batch 8 gathers for MLP; .cg bypasses L1 allocation (L2-resident x).
        unsigned v[8];
        #pragma unroll
        for (int j = 0; j < 8; j++) {
            const int nb = __shfl_sync(0xffffffffu, my_idx, c * 8 + j);
            v[j] = __ldcg(xb + (size_t)nb * ROW_H2);
        }
        // Max: exact selection in fp16.
        #pragma unroll
        for (int j = 0; j < 8; j++) mx = __hmax2(mx, u2h(v[j]));
        // Sum: tree-of-8 in fp16, then promote to fp32 once per chunk.
        __half2 s01 = __hadd2(u2h(v[0]), u2h(v[1]));
        __half2 s23 = __hadd2(u2h(v[2]), u2h(v[3]));
        __half2 s45 = __hadd2(u2h(v[4]), u2h(v[5]));
        __half2 s67 = __hadd2(u2h(v[6]), u2h(v[7]));
        __half2 s   = __hadd2(__hadd2(s01, s23), __hadd2(s45, s67));
        const float2 sf = __half22float2(s);
        sum.x += sf.x;
        sum.y += sf.y;
    }

    float* o = out + (size_t)row * (2 * FF);
    reinterpret_cast<float2*>(o)[lane] =
        make_float2(sum.x * (1.0f / KK), sum.y * (1.0f / KK));      // mean half
    const float2 mf = __half22float2(mx);
    reinterpret_cast<float2*>(o + FF)[lane] = mf;                   // max half
}

extern "C" void kernel_launch(void* const* d_in, const int* in_sizes, int n_in,
                              void* d_out, int out_size) {
    const float* x    = (const float*)d_in[0];
    const int*   idxs = (const int*)d_in[1];
    float*       out  = (float*)d_out;

    const int n4 = VV * FF / 4;
    convert_kernel<<<(n4 + 255) / 256, 256>>>(x);

    const int threads = 256;
    const int rows_per_block = threads / 32;
    const int blocks = (VV + rows_per_block - 1) / rows_per_block;
    collect_nbr_kernel<<<blocks, threads>>>(idxs, out);
}

// round 10
// speedup vs baseline: 1.0483x; 1.0483x over previous
#include <cuda_runtime.h>
#include <cuda_fp16.h>
#include <math.h>

// CollectNeighbourAverageAndMax: out[v] = concat(mean_k x[idx[v,k]], max_k x[idx[v,k]])
// V=100000, K=32, F=64.
//
// R9: R4/R6 structure, but index broadcast WITHOUT shuffles.
// Model (calibrated on R1-R6): l1tex busy ~= 0.9 cyc/gather-wavefront
//   + ~1 cyc/SHFL (shuffle shares the MIO/L1tex pipe) + ~10 cyc/row stores.
// The 32 SHFLs/row were ~45% of L1 busy. Replace them with 8 uniform-address
// int4 loads of the index row (same address in all lanes -> 1 broadcast
// wavefront each, 7 of 8 are L1 hits on the same 128B line).
//  - fp16 mirror (12.8MB static): one row = 128B = one L1 line.
//  - one warp per output row; lane l owns features (2l, 2l+1) as one half2.
//  - 32 warp-wide LDG.32 gathers (one line / one wavefront each).
//  - max in half2 (exact); sum tree-of-4 fp16 then fp32 promote per chunk.

#define VV 100000
#define KK 32
#define FF 64
#define ROW_H2 (FF / 2)   // 32 half2 per row

__device__ __half2 g_xh[(size_t)VV * ROW_H2];   // 12.8 MB static scratch

// ---- prepass: fp32 -> fp16 conversion (streaming hints) -------------------
__global__ void convert_kernel(const float* __restrict__ x) {
    const int i = blockIdx.x * blockDim.x + threadIdx.x;  // one float4 -> two half2
    const int n4 = VV * FF / 4;
    if (i >= n4) return;
    const float4 v = __ldcg(reinterpret_cast<const float4*>(x) + i);
    __half2 h0 = __floats2half2_rn(v.x, v.y);
    __half2 h1 = __floats2half2_rn(v.z, v.w);
    unsigned u0 = *reinterpret_cast<unsigned*>(&h0);
    unsigned u1 = *reinterpret_cast<unsigned*>(&h1);
    __stcg(reinterpret_cast<uint2*>(g_xh) + i, make_uint2(u0, u1));
}

__device__ __forceinline__ __half2 u2h(unsigned u) {
    return *reinterpret_cast<__half2*>(&u);
}

// ---- main gather/reduce ---------------------------------------------------
__global__ __launch_bounds__(256, 8)
void collect_nbr_kernel(const int* __restrict__ idxs,
                        float* __restrict__ out) {
    const int row  = (blockIdx.x * blockDim.x + threadIdx.x) >> 5;
    const int lane = threadIdx.x & 31;
    if (row >= VV) return;

    float2  sum = make_float2(0.f, 0.f);
    __half2 mx  = u2h(0xFBFFFBFFu);    // half2(-65504, -65504)

    const unsigned* __restrict__ xb =
        reinterpret_cast<const unsigned*>(g_xh) + lane;  // lane's slot in any row
    const int4* __restrict__ idxq =
        reinterpret_cast<const int4*>(idxs + (size_t)row * KK);

    #pragma unroll
    for (int c = 0; c < KK / 8; c++) {
        // Uniform-address index loads: 1 broadcast wavefront each, no SHFL.
        const int4 qa = __ldg(idxq + 2 * c);
        const int4 qb = __ldg(idxq + 2 * c + 1);
        // 8 independent gathers in flight (one 128B line / 1 wavefront each).
        unsigned v0 = __ldg(xb + (size_t)qa.x * ROW_H2);
        unsigned v1 = __ldg(xb + (size_t)qa.y * ROW_H2);
        unsigned v2 = __ldg(xb + (size_t)qa.z * ROW_H2);
        unsigned v3 = __ldg(xb + (size_t)qa.w * ROW_H2);
        unsigned v4 = __ldg(xb + (size_t)qb.x * ROW_H2);
        unsigned v5 = __ldg(xb + (size_t)qb.y * ROW_H2);
        unsigned v6 = __ldg(xb + (size_t)qb.z * ROW_H2);
        unsigned v7 = __ldg(xb + (size_t)qb.w * ROW_H2);

        mx = __hmax2(mx, u2h(v0));
        mx = __hmax2(mx, u2h(v1));
        mx = __hmax2(mx, u2h(v2));
        mx = __hmax2(mx, u2h(v3));
        mx = __hmax2(mx, u2h(v4));
        mx = __hmax2(mx, u2h(v5));
        mx = __hmax2(mx, u2h(v6));
        mx = __hmax2(mx, u2h(v7));

        __half2 s01 = __hadd2(u2h(v0), u2h(v1));
        __half2 s23 = __hadd2(u2h(v2), u2h(v3));
        __half2 s45 = __hadd2(u2h(v4), u2h(v5));
        __half2 s67 = __hadd2(u2h(v6), u2h(v7));
        __half2 s   = __hadd2(__hadd2(s01, s23), __hadd2(s45, s67));
        const float2 sf = __half22float2(s);
        sum.x += sf.x;
        sum.y += sf.y;
    }

    float* o = out + (size_t)row * (2 * FF);
    reinterpret_cast<float2*>(o)[lane] =
        make_float2(sum.x * (1.0f / KK), sum.y * (1.0f / KK));      // mean half
    const float2 mf = __half22float2(mx);
    reinterpret_cast<float2*>(o + FF)[lane] = mf;                   // max half
}

extern "C" void kernel_launch(void* const* d_in, const int* in_sizes, int n_in,
                              void* d_out, int out_size) {
    const float* x    = (const float*)d_in[0];
    const int*   idxs = (const int*)d_in[1];
    float*       out  = (float*)d_out;

    const int n4 = VV * FF / 4;
    convert_kernel<<<(n4 + 255) / 256, 256>>>(x);

    const int threads = 256;
    const int rows_per_block = threads / 32;
    const int blocks = (VV + rows_per_block - 1) / rows_per_block;
    collect_nbr_kernel<<<blocks, threads>>>(idxs, out);
}